// round 6
// baseline (speedup 1.0000x reference)
#include <cuda_runtime.h>

// BKT_RNN: B=8192, T=2048, H=4, X=1.
// R6: R4 mapping (4 lanes/row, closed-form BKT latent) + 2-way ILP:
// each thread advances TWO independent rows so their dependency chains
// (shfl -> dot -> ex2 -> rcp) overlap in the scheduler. 512 one-warp blocks,
// 16 rows per warp. Loss via per-warp slots (no zeroing kernel).

#define TT 2048
#define BB 8192
#define NWARP (BB / 16)   // 512

__device__ float g_part[NWARP];

__device__ __forceinline__ float ex2f(float v) {
    float r; asm("ex2.approx.f32 %0, %1;" : "=f"(r) : "f"(v)); return r;
}
__device__ __forceinline__ float rcpf(float v) {
    float r; asm("rcp.approx.f32 %0, %1;" : "=f"(r) : "f"(v)); return r;
}
__device__ __forceinline__ float lg2f(float v) {
    float r; asm("lg2.approx.f32 %0, %1;" : "=f"(r) : "f"(v)); return r;
}

__global__ void __launch_bounds__(32) k_bkt(
    const float* __restrict__ x,   const float* __restrict__ y,
    const float* __restrict__ Wxh, const float* __restrict__ Whh,
    const float* __restrict__ bh,  const float* __restrict__ Wy,
    const float* __restrict__ by,  const float* __restrict__ prior,
    float* __restrict__ corrects,  float* __restrict__ latents)
{
    const unsigned FULL = 0xffffffffu;
    const int lane = threadIdx.x;
    const int j = lane & 3;                    // unit index within row
    const int g = lane >> 2;                   // group 0..7
    const int b0 = blockIdx.x * 16 + g;        // row A
    const int b1 = b0 + 8;                     // row B (independent)

    // Lane j holds column j of the weights, pre-scaled by -log2(e):
    // sigmoid(z) = rcp(1 + ex2(z_scaled)). Shared by both rows.
    const float NL2E = -1.4426950408889634f;
    float Ac[4], Wc[4];
    #pragma unroll
    for (int i = 0; i < 4; i++) {
        Ac[i] = NL2E * __ldg(Wy  + i * 4 + j);
        Wc[i] = NL2E * __ldg(Whh + i * 4 + j);
    }
    const float avj = NL2E * __ldg(by  + j);
    const float bhj = NL2E * __ldg(bh  + j);
    const float wxj = NL2E * __ldg(Wxh + j);

    float hA = 0.f, hB = 0.f;
    float latA = __ldg(prior), latB = latA;
    float lsum = 0.f;

    const float4* xpA = (const float4*)(x + (size_t)b0 * TT);
    const float4* ypA = (const float4*)(y + (size_t)b0 * TT);
    const float4* xpB = (const float4*)(x + (size_t)b1 * TT);
    const float4* ypB = (const float4*)(y + (size_t)b1 * TT);
    float2* cpA = (float2*)(corrects + (size_t)b0 * TT);
    float2* lpA = (float2*)(latents  + (size_t)b0 * TT);
    float2* cpB = (float2*)(corrects + (size_t)b1 * TT);
    float2* lpB = (float2*)(latents  + (size_t)b1 * TT);

    // Prime pipeline (chunk 0 = 8 timesteps each row).
    float4 xaA = __ldcs(xpA + 0), xbA = __ldcs(xpA + 1);
    float4 yaA = __ldcs(ypA + 0), ybA = __ldcs(ypA + 1);
    float4 xaB = __ldcs(xpB + 0), xbB = __ldcs(xpB + 1);
    float4 yaB = __ldcs(ypB + 0), ybB = __ldcs(ypB + 1);

    const int NCHUNK = TT / 8;
    for (int c = 0; c < NCHUNK; ++c) {
        float xvA[8] = {xaA.x, xaA.y, xaA.z, xaA.w, xbA.x, xbA.y, xbA.z, xbA.w};
        float yvA[8] = {yaA.x, yaA.y, yaA.z, yaA.w, ybA.x, ybA.y, ybA.z, ybA.w};
        float xvB[8] = {xaB.x, xaB.y, xaB.z, xaB.w, xbB.x, xbB.y, xbB.z, xbB.w};
        float yvB[8] = {yaB.x, yaB.y, yaB.z, yaB.w, ybB.x, ybB.y, ybB.z, ybB.w};

        if (c + 1 < NCHUNK) {   // prefetch next chunk under compute
            xaA = __ldcs(xpA + 2 * c + 2); xbA = __ldcs(xpA + 2 * c + 3);
            yaA = __ldcs(ypA + 2 * c + 2); ybA = __ldcs(ypA + 2 * c + 3);
            xaB = __ldcs(xpB + 2 * c + 2); xbB = __ldcs(xpB + 2 * c + 3);
            yaB = __ldcs(ypB + 2 * c + 2); ybB = __ldcs(ypB + 2 * c + 3);
        }

        float cbA[8], lbA[8], cbB[8], lbB[8];
        float prodA = 1.f, prodB = 1.f;

        #pragma unroll
        for (int k = 0; k < 8; k++) {
            // ---- gather h for both rows (independent shfl rounds) ----
            const float a0 = __shfl_sync(FULL, hA, 0, 4);
            const float a1 = __shfl_sync(FULL, hA, 1, 4);
            const float a2 = __shfl_sync(FULL, hA, 2, 4);
            const float a3 = __shfl_sync(FULL, hA, 3, 4);
            const float b0_ = __shfl_sync(FULL, hB, 0, 4);
            const float b1_ = __shfl_sync(FULL, hB, 1, 4);
            const float b2_ = __shfl_sync(FULL, hB, 2, 4);
            const float b3_ = __shfl_sync(FULL, hB, 3, 4);

            // ---- p_j = sigmoid(h @ Wy[:,j] + by[j]) (tree dots) ----
            const float zpA = fmaf(a1, Ac[1], fmaf(a0, Ac[0], avj)) +
                              fmaf(a2, Ac[2], a3 * Ac[3]);
            const float zpB = fmaf(b1_, Ac[1], fmaf(b0_, Ac[0], avj)) +
                              fmaf(b2_, Ac[2], b3_ * Ac[3]);
            const float pA = rcpf(1.f + ex2f(zpA));
            const float pB = rcpf(1.f + ex2f(zpB));

            // ---- h update (OLD h) ----
            const float zhA = fmaf(a0, Wc[0], fmaf(xvA[k], wxj, bhj)) +
                              fmaf(a2, Wc[2], fmaf(a3, Wc[3], a1 * Wc[1]));
            const float zhB = fmaf(b0_, Wc[0], fmaf(xvB[k], wxj, bhj)) +
                              fmaf(b2_, Wc[2], fmaf(b3_, Wc[3], b1_ * Wc[1]));
            hA = rcpf(1.f + ex2f(zhA));
            hB = rcpf(1.f + ex2f(zhB));

            // ---- gather p = (l,f,g,s) for both rows ----
            const float lA = __shfl_sync(FULL, pA, 0, 4);
            const float fA = __shfl_sync(FULL, pA, 1, 4);
            const float gA = __shfl_sync(FULL, pA, 2, 4);
            const float sA = __shfl_sync(FULL, pA, 3, 4);
            const float lB = __shfl_sync(FULL, pB, 0, 4);
            const float fB = __shfl_sync(FULL, pB, 1, 4);
            const float gB = __shfl_sync(FULL, pB, 2, 4);
            const float sB = __shfl_sync(FULL, pB, 3, 4);

            // ---- closed-form BKT (exact: m_t == latent) ----
            const float corA = fmaf(latA, 1.f - sA - gA, gA);
            latA             = fmaf(latA, 1.f - fA - lA, lA);
            const float corB = fmaf(latB, 1.f - sB - gB, gB);
            latB             = fmaf(latB, 1.f - fB - lB, lB);

            // ---- loss: y in {0,1}; lg2 amortized over 4 steps ----
            const float cA  = fminf(fmaxf(corA, 1e-7f), 1.0f - 1e-7f);
            const float cB  = fminf(fmaxf(corB, 1e-7f), 1.0f - 1e-7f);
            prodA *= (yvA[k] != 0.f) ? cA : (1.f - cA);
            prodB *= (yvB[k] != 0.f) ? cB : (1.f - cB);
            if ((k & 3) == 3) {
                lsum += lg2f(prodA) + lg2f(prodB);
                prodA = 1.f; prodB = 1.f;
            }

            cbA[k] = corA; lbA[k] = latA;
            cbB[k] = corB; lbB[k] = latB;
        }

        // Lane j stores elements {2j, 2j+1}: 32B contiguous per group.
        #define SEL8(v) ((j & 2) ? ((j & 1) ? v[6] : v[4]) : ((j & 1) ? v[2] : v[0]))
        #define SEL8b(v) ((j & 2) ? ((j & 1) ? v[7] : v[5]) : ((j & 1) ? v[3] : v[1]))
        __stcs(cpA + c * 4 + j, make_float2(SEL8(cbA), SEL8b(cbA)));
        __stcs(lpA + c * 4 + j, make_float2(SEL8(lbA), SEL8b(lbA)));
        __stcs(cpB + c * 4 + j, make_float2(SEL8(cbB), SEL8b(cbB)));
        __stcs(lpB + c * 4 + j, make_float2(SEL8(lbB), SEL8b(lbB)));
        #undef SEL8
        #undef SEL8b
    }

    // Warp reduce (each row counted 4x across its lanes) -> fixed slot.
    #pragma unroll
    for (int o = 16; o > 0; o >>= 1)
        lsum += __shfl_xor_sync(FULL, lsum, o);
    if (lane == 0)
        g_part[blockIdx.x] = lsum;
}

__global__ void k_final(float* __restrict__ loss) {
    __shared__ double s[NWARP];
    const int t = threadIdx.x;
    s[t] = (double)g_part[t];
    __syncthreads();
    for (int o = NWARP / 2; o > 0; o >>= 1) {
        if (t < o) s[t] += s[t + o];
        __syncthreads();
    }
    if (t == 0)
        loss[0] = (float)(-0.6931471805599453 * s[0] /
                          (4.0 * (double)BB * (double)TT));
}

extern "C" void kernel_launch(void* const* d_in, const int* in_sizes, int n_in,
                              void* d_out, int out_size) {
    const float* x     = (const float*)d_in[0];
    const float* y     = (const float*)d_in[1];
    const float* Wxh   = (const float*)d_in[2];
    const float* Whh   = (const float*)d_in[3];
    const float* bh    = (const float*)d_in[4];
    const float* Wy    = (const float*)d_in[5];
    const float* by    = (const float*)d_in[6];
    const float* prior = (const float*)d_in[7];

    float* corrects = (float*)d_out;
    float* latents  = (float*)d_out + (size_t)BB * TT;
    float* loss     = (float*)d_out + 2 * (size_t)BB * TT;

    k_bkt<<<NWARP, 32>>>(x, y, Wxh, Whh, bh, Wy, by, prior, corrects, latents);
    k_final<<<1, NWARP>>>(loss);
}

// round 7
// speedup vs baseline: 1.3181x; 1.3181x over previous
#include <cuda_runtime.h>

// BKT_RNN: B=8192, T=2048, H=4, X=1.
// R7: 4 lanes/row, 1024 one-warp blocks (the only winning occupancy), with
// shuffle count cut 8 -> 5 per step:
//   - h all-gather: scalar shfl_xor(1) + u64 shfl_xor(2)  (3 SASS SHFL),
//     lane order [h_j, h_j^1, h_j^2, h_j^3] absorbed into weight permutation.
//   - p: one shfl_xor(1) gives lanes 0/1 (l,f), lanes 2/3 (g,s); both the
//     latent update and `correct` are res = base + lat*(1-own-oth); one
//     shfl(lat,0,4) broadcasts lane0's latent.
// Lanes 0/1 store the latent series, lanes 2/3 the correct series (one
// STG.128 per lane per 8-step chunk). Loss fused via last-block-done.

#define TT 2048
#define BB 8192
#define NBLK (BB / 8)   // 1024 one-warp blocks

typedef unsigned long long u64;

__device__ float    g_part[NBLK];
__device__ unsigned g_done = 0;

__device__ __forceinline__ float ex2f(float v) {
    float r; asm("ex2.approx.f32 %0, %1;" : "=f"(r) : "f"(v)); return r;
}
__device__ __forceinline__ float rcpf(float v) {
    float r; asm("rcp.approx.f32 %0, %1;" : "=f"(r) : "f"(v)); return r;
}
__device__ __forceinline__ float lg2f(float v) {
    float r; asm("lg2.approx.f32 %0, %1;" : "=f"(r) : "f"(v)); return r;
}
__device__ __forceinline__ u64 pack2(float lo, float hi) {
    u64 r; asm("mov.b64 %0, {%1, %2};" : "=l"(r) : "f"(lo), "f"(hi)); return r;
}
__device__ __forceinline__ void unpack2(u64 v, float& lo, float& hi) {
    asm("mov.b64 {%0, %1}, %2;" : "=f"(lo), "=f"(hi) : "l"(v));
}

__global__ void __launch_bounds__(32) k_bkt(
    const float* __restrict__ x,   const float* __restrict__ y,
    const float* __restrict__ Wxh, const float* __restrict__ Whh,
    const float* __restrict__ bh,  const float* __restrict__ Wy,
    const float* __restrict__ by,  const float* __restrict__ prior,
    float* __restrict__ corrects,  float* __restrict__ latents,
    float* __restrict__ loss)
{
    const unsigned FULL = 0xffffffffu;
    const int lane = threadIdx.x;
    const int j = lane & 3;                    // unit index within row
    const int b = blockIdx.x * 8 + (lane >> 2);

    // Weights pre-scaled by -log2(e) (sigmoid(z) = rcp(1+ex2(z'))), rows
    // permuted to the gather order [j, j^1, j^2, j^3].
    const float NL2E = -1.4426950408889634f;
    float Ac[4], Wc[4];
    #pragma unroll
    for (int i = 0; i < 4; i++) {
        const int src = j ^ i;
        Ac[i] = NL2E * __ldg(Wy  + src * 4 + j);
        Wc[i] = NL2E * __ldg(Whh + src * 4 + j);
    }
    const float avj = NL2E * __ldg(by  + j);
    const float bhj = NL2E * __ldg(bh  + j);
    const float wxj = NL2E * __ldg(Wxh + j);

    float hj   = 0.f;
    float lat  = __ldg(prior);     // authoritative on lane 0 of each group
    float lsum = 0.f;
    const bool  odd  = (lane & 1) != 0;
    const bool  hi2  = (lane & 2) != 0;   // lanes 2,3 produce `correct`

    const float4* xp = (const float4*)(x + (size_t)b * TT);
    const float4* yp = (const float4*)(y + (size_t)b * TT);
    // Lanes 0/1 write latents, lanes 2/3 write corrects. One float4 each.
    float4* op = (float4*)((hi2 ? corrects : latents) + (size_t)b * TT);

    // Prime pipeline (chunk 0 = 8 timesteps).
    float4 xa = __ldcs(xp + 0), xb = __ldcs(xp + 1);
    float4 ya = __ldcs(yp + 0), yb = __ldcs(yp + 1);

    const int NCHUNK = TT / 8;
    for (int c = 0; c < NCHUNK; ++c) {
        float xv[8] = {xa.x, xa.y, xa.z, xa.w, xb.x, xb.y, xb.z, xb.w};
        float yv[8] = {ya.x, ya.y, ya.z, ya.w, yb.x, yb.y, yb.z, yb.w};

        if (c + 1 < NCHUNK) {   // prefetch next chunk under compute
            xa = __ldcs(xp + 2 * c + 2); xb = __ldcs(xp + 2 * c + 3);
            ya = __ldcs(yp + 2 * c + 2); yb = __ldcs(yp + 2 * c + 3);
        }

        float rb[8];
        float prod = 1.f;

        #pragma unroll
        for (int k = 0; k < 8; k++) {
            // ---- h all-gather: 3 SASS shuffles ----
            const float hoth = __shfl_xor_sync(FULL, hj, 1);
            const u64   hpk  = pack2(hj, hoth);
            const u64   hrcv = __shfl_xor_sync(FULL, hpk, 2);
            float hc, hd; unpack2(hrcv, hc, hd);
            // order on this lane: [hj, hoth, hc, hd] = h[j^0..j^3]

            // ---- dots (weights pre-permuted) ----
            const float zp = fmaf(hoth, Ac[1], fmaf(hj, Ac[0], avj)) +
                             fmaf(hc, Ac[2], hd * Ac[3]);
            const float zh = fmaf(hoth, Wc[1],
                                  fmaf(hj, Wc[0], fmaf(xv[k], wxj, bhj))) +
                             fmaf(hc, Wc[2], hd * Wc[3]);

            const float pj = rcpf(1.f + ex2f(zp));
            hj             = rcpf(1.f + ex2f(zh));

            // ---- latent / correct: unified FMA form ----
            // lanes 0,1: own/oth = (l,f) -> res = l + lat*(1-l-f) = lat'
            // lanes 2,3: own/oth = (g,s) -> res = g + lat*(1-g-s) = correct
            const float po   = __shfl_xor_sync(FULL, pj, 1);
            const float coef = 1.f - pj - po;
            const float base = odd ? po : pj;
            const float latc = __shfl_sync(FULL, lat, 0, 4);  // old latent
            const float res  = fmaf(latc, coef, base);
            lat = res;              // only lane 0's copy is ever read
            rb[k] = res;

            // ---- loss (valid on lanes 2,3; gated at the lg2) ----
            const float cc  = fminf(fmaxf(res, 1e-7f), 1.0f - 1e-7f);
            prod *= (yv[k] != 0.f) ? cc : (1.f - cc);
            if ((k & 3) == 3) {
                lsum += hi2 ? lg2f(prod) : 0.f;
                prod = 1.f;
            }
        }

        // Even lanes store elements 0..3, odd lanes 4..7 of their series.
        const float4 v = odd ? make_float4(rb[4], rb[5], rb[6], rb[7])
                             : make_float4(rb[0], rb[1], rb[2], rb[3]);
        __stcs(op + 2 * c + (odd ? 1 : 0), v);
    }

    // Warp reduce (each row counted 2x: lanes 2 and 3) -> per-block slot.
    #pragma unroll
    for (int o = 16; o > 0; o >>= 1)
        lsum += __shfl_xor_sync(FULL, lsum, o);
    if (lane == 0)
        g_part[blockIdx.x] = lsum;
    __threadfence();

    // Last-block-done reduction (fused finalize).
    unsigned ticket = 0;
    if (lane == 0) ticket = atomicAdd(&g_done, 1u);
    ticket = __shfl_sync(FULL, ticket, 0);
    if (ticket == NBLK - 1) {
        double acc = 0.0;
        for (int i = lane; i < NBLK; i += 32)
            acc += (double)g_part[i];
        #pragma unroll
        for (int o = 16; o > 0; o >>= 1)
            acc += __shfl_xor_sync(FULL, acc, o);
        if (lane == 0) {
            loss[0] = (float)(-0.6931471805599453 * acc /
                              (2.0 * (double)BB * (double)TT));
            g_done = 0;   // re-arm for the next graph replay
        }
    }
}

extern "C" void kernel_launch(void* const* d_in, const int* in_sizes, int n_in,
                              void* d_out, int out_size) {
    const float* x     = (const float*)d_in[0];
    const float* y     = (const float*)d_in[1];
    const float* Wxh   = (const float*)d_in[2];
    const float* Whh   = (const float*)d_in[3];
    const float* bh    = (const float*)d_in[4];
    const float* Wy    = (const float*)d_in[5];
    const float* by    = (const float*)d_in[6];
    const float* prior = (const float*)d_in[7];

    float* corrects = (float*)d_out;
    float* latents  = (float*)d_out + (size_t)BB * TT;
    float* loss     = (float*)d_out + 2 * (size_t)BB * TT;

    k_bkt<<<NBLK, 32>>>(x, y, Wxh, Whh, bh, Wy, by, prior,
                        corrects, latents, loss);
}